// round 16
// baseline (speedup 1.0000x reference)
#include <cuda_runtime.h>
#include <cuda_bf16.h>
#include <cuda_fp16.h>
#include <cstdint>

#define B_ 16
#define S_ 1024
#define N_ 4096
#define C_ 768
#define O_ 256
#define M_ (B_ * S_)   // 16384

// ---------------------------------------------------------------------------
// Scratch (__device__ globals; allocation-free rule).
// ---------------------------------------------------------------------------
__device__ int      g_idx[M_];
__device__ __half   g_Bf[O_ * C_];

// ---------------------------------------------------------------------------
// Base-ISA (compute_103-safe) PTX helpers
// ---------------------------------------------------------------------------
__device__ __forceinline__ uint32_t smem_u32(const void* p) {
    uint32_t a;
    asm("{ .reg .u64 t; cvta.to.shared.u64 t, %1; cvt.u32.u64 %0, t; }" : "=r"(a) : "l"(p));
    return a;
}
__device__ __forceinline__ void cp16(uint32_t dst, const void* src) {
    asm volatile("cp.async.cg.shared.global [%0], [%1], 16;"
                 :: "r"(dst), "l"(src) : "memory");
}
#define CP_COMMIT() asm volatile("cp.async.commit_group;" ::: "memory")
#define CP_WAIT(n)  asm volatile("cp.async.wait_group %0;" :: "n"(n) : "memory")

__device__ __forceinline__ void ldsm4(uint32_t* r, uint32_t addr) {
    asm volatile("ldmatrix.sync.aligned.m8n8.x4.shared.b16 {%0,%1,%2,%3}, [%4];"
                 : "=r"(r[0]), "=r"(r[1]), "=r"(r[2]), "=r"(r[3]) : "r"(addr));
}
__device__ __forceinline__ void ldsm4t(uint32_t* r, uint32_t addr) {
    asm volatile("ldmatrix.sync.aligned.m8n8.x4.trans.shared.b16 {%0,%1,%2,%3}, [%4];"
                 : "=r"(r[0]), "=r"(r[1]), "=r"(r[2]), "=r"(r[3]) : "r"(addr));
}
__device__ __forceinline__ void mma_f16(float* c, const uint32_t* a, const uint32_t* b) {
    asm volatile("mma.sync.aligned.m16n8k16.row.col.f32.f16.f16.f32 "
                 "{%0,%1,%2,%3}, {%4,%5,%6,%7}, {%8,%9}, {%0,%1,%2,%3};"
                 : "+f"(c[0]), "+f"(c[1]), "+f"(c[2]), "+f"(c[3])
                 : "r"(a[0]), "r"(a[1]), "r"(a[2]), "r"(a[3]), "r"(b[0]), "r"(b[1]));
}

// ---- packed fp32x2 (per-lane IEEE rn, identical to __fmul_rn/__fadd_rn) ----
typedef unsigned long long ull;
__device__ __forceinline__ ull pk2(float a, float b) {
    ull r;
    asm("mov.b64 %0, {%1, %2};" : "=l"(r) : "r"(__float_as_uint(a)), "r"(__float_as_uint(b)));
    return r;
}
__device__ __forceinline__ ull bc2(float v) {
    ull r;
    asm("mov.b64 %0, {%1, %1};" : "=l"(r) : "r"(__float_as_uint(v)));
    return r;
}
__device__ __forceinline__ ull mul2(ull a, ull b) {
    ull d; asm("mul.rn.f32x2 %0, %1, %2;" : "=l"(d) : "l"(a), "l"(b)); return d;
}
__device__ __forceinline__ ull add2(ull a, ull b) {
    ull d; asm("add.rn.f32x2 %0, %1, %2;" : "=l"(d) : "l"(a), "l"(b)); return d;
}
__device__ __forceinline__ ull sub2(ull a, ull b) {
    return add2(a, b ^ 0x8000000080000000ull);
}
__device__ __forceinline__ void unpk2(float& lo, float& hi, ull v) {
    unsigned a, b;
    asm("mov.b64 {%0, %1}, %2;" : "=r"(a), "=r"(b) : "l"(v));
    lo = __uint_as_float(a); hi = __uint_as_float(b);
}
__device__ __forceinline__ ull mkkey(float d2, int n) {
    const unsigned u = __float_as_uint(d2);
    const unsigned ord = u ^ (((unsigned)((int)u >> 31)) | 0x80000000u);
    return ((ull)ord << 32) | (unsigned)n;
}

// ---------------------------------------------------------------------------
// Kernel 1: argmin, f32x2-packed (proven round-13 version).
// ---------------------------------------------------------------------------
__global__ __launch_bounds__(256) void argmin_kernel(const float* __restrict__ seed,
                                                     const float* __restrict__ pl) {
    extern __shared__ float4 p4[];                 // 4096 * 16B = 64KB
    __shared__ ull mg[8][64];
    const int bx   = blockIdx.x;
    const int b    = bx >> 4;
    const int tid  = threadIdx.x;
    const int w    = tid >> 5;
    const int lane = tid & 31;
    const int sbase = (bx & 15) << 6;

    for (int n = tid; n < N_; n += 256) {
        const float* pp = pl + ((size_t)b * N_ + n) * 3;
        const float p0 = pp[0], p1 = pp[1], p2 = pp[2];
        const float spp = __fadd_rn(__fadd_rn(__fmul_rn(p0, p0), __fmul_rn(p1, p1)),
                                    __fmul_rn(p2, p2));
        p4[n] = make_float4(p0, p1, p2, spp);
    }

    const float* sa = seed + ((size_t)b * S_ + sbase + lane) * 3;
    const float* sc = seed + ((size_t)b * S_ + sbase + 32 + lane) * 3;
    const float xa0 = sa[0], xa1 = sa[1], xa2 = sa[2];
    const float xb0 = sc[0], xb1 = sc[1], xb2 = sc[2];
    const float sxa = __fadd_rn(__fadd_rn(__fmul_rn(xa0, xa0), __fmul_rn(xa1, xa1)),
                                __fmul_rn(xa2, xa2));
    const float sxb = __fadd_rn(__fadd_rn(__fmul_rn(xb0, xb0), __fmul_rn(xb1, xb1)),
                                __fmul_rn(xb2, xb2));
    const ull X0 = pk2(xa0, xb0), X1 = pk2(xa1, xb1), X2 = pk2(xa2, xb2);
    const ull SX = pk2(sxa, sxb);
    __syncthreads();

    float bestA[2] = {3.402823466e38f, 3.402823466e38f};
    float bestB[2] = {3.402823466e38f, 3.402823466e38f};
    int   iA[2] = {0, 0}, iB[2] = {0, 0};

    const int nb = w * 512;
#pragma unroll 2
    for (int n0 = 0; n0 < 512; n0 += 2) {
#pragma unroll
        for (int j = 0; j < 2; j++) {
            const int n = nb + n0 + j;
            const float4 q = p4[n];
            const ull QX = bc2(q.x), QY = bc2(q.y), QZ = bc2(q.z), QW = bc2(q.w);
            const ull DOT = add2(add2(mul2(X0, QX), mul2(X1, QY)), mul2(X2, QZ));
            const ull D2  = add2(sub2(SX, add2(DOT, DOT)), QW);
            float d2a, d2b;
            unpk2(d2a, d2b, D2);
            if (d2a < bestA[j]) { bestA[j] = d2a; iA[j] = n; }
            if (d2b < bestB[j]) { bestB[j] = d2b; iB[j] = n; }
        }
    }

    ull ka = mkkey(bestA[0], iA[0]);
    { const ull k1 = mkkey(bestA[1], iA[1]); if (k1 < ka) ka = k1; }
    ull kb = mkkey(bestB[0], iB[0]);
    { const ull k1 = mkkey(bestB[1], iB[1]); if (k1 < kb) kb = k1; }
    mg[w][lane]      = ka;
    mg[w][lane + 32] = kb;
    __syncthreads();

    if (tid < 64) {
        ull k = mg[0][tid];
#pragma unroll
        for (int r = 1; r < 8; r++) { const ull k2 = mg[r][tid]; if (k2 < k) k = k2; }
        g_idx[b * S_ + sbase + tid] = (int)(k & 0xFFFFFFFFu);
    }
}

// ---------------------------------------------------------------------------
// Kernel 2: round W to fp16.
// ---------------------------------------------------------------------------
__global__ __launch_bounds__(256) void wconv_kernel(const float* __restrict__ W) {
    const int i = blockIdx.x * 256 + threadIdx.x;
    if (i < O_ * C_) g_Bf[i] = __float2half(W[i]);
}

// ---------------------------------------------------------------------------
// Kernel 3: FUSED gather+GEMM: D[m][n] = sum_c f16(f[b,c,idx[m]]) * Bf[n][c].
// CTA 256m x 64n, warps 4m x 2n, warp tile m64 x n32, k16 chunks.
// Grid (4 n, 64 m): 256 CTAs, 2/SM -> ONE wave; the 4 n-tiles per m-tile and
// 4 m-tiles per batch are co-resident -> L2 dedups the scattered f reads
// (unique DRAM ~174MB; g_Af scratch eliminated entirely).
// A path: thread owns one m (idx in a register); per chunk 16 scattered LDG
// (rows kc*16..+15), cvt fp16, STS into the SAME 528B-stride layout the
// proven ldsm.trans addressing expects. A smem double-buffered; staged-reg
// prefetch distance 1 chunk. B path: cp.async 8-stage ring (proven).
// smem: A 2x8448 = 16896 | B 8x3072 = 24576 -> 41472B.
// ---------------------------------------------------------------------------
#define A_BUF  8448
#define B_OFF  16896
#define B_STG  3072
#define GEMM_SMEM (B_OFF + 8 * B_STG)

__global__ __launch_bounds__(256, 2) void gemm_kernel(const float* __restrict__ f,
                                                      const float* __restrict__ bias,
                                                      float* __restrict__ out) {
    extern __shared__ char smem[];
    const uint32_t sb = smem_u32(smem);
    __half* asm0 = reinterpret_cast<__half*>(smem);            // A buf0 (row stride 264 halves)
    __half* asm1 = reinterpret_cast<__half*>(smem + A_BUF);    // A buf1
    const int tid  = threadIdx.x;
    const int lane = tid & 31;
    const int wid  = tid >> 5;
    const int warp_m = wid & 3;      // 4 m-warps (m64 each)
    const int warp_n = wid >> 2;     // 2 n-warps (n32 each)
    const int n0 = blockIdx.x * 64;  // n-tile fastest -> co-resident dedup
    const int m0 = blockIdx.y * 256;
    const int b  = m0 >> 10;

    // A: this thread owns seed m = m0 + tid; one idx register.
    const int idxv = g_idx[m0 + tid];
    const float* fb = f + (size_t)b * C_ * N_ + idxv;   // + c*N_ selects channel row

    // B cp.async assignment (proven): 64 rows x 2 segs, threads 0..127.
    const int brow = (tid >> 1) & 63;
    const int bseg = tid & 1;
    const bool bact = tid < 128;
    const __half* gB = g_Bf + (size_t)(n0 + brow) * C_ + bseg * 8;
    const uint32_t dB = (uint32_t)(brow * 48 + bseg * 16);

#define ISSUEB(kc, stg)                                                   \
    do {                                                                  \
        if (bact) cp16(sb + B_OFF + (stg) * B_STG + dB, gB + (kc) * 16);  \
    } while (0)

    // ---- Prologue ----
    float areg[16];
    // A chunk 0 -> regs -> buf0
#pragma unroll
    for (int r = 0; r < 16; r++) areg[r] = __ldg(fb + (size_t)r * N_);
#pragma unroll
    for (int r = 0; r < 16; r++) asm0[r * 264 + tid] = __float2half(areg[r]);
    // A chunk 1 -> staging regs
#pragma unroll
    for (int r = 0; r < 16; r++) areg[r] = __ldg(fb + (size_t)(16 + r) * N_);

    ISSUEB(0, 0); CP_COMMIT();
    ISSUEB(1, 1); CP_COMMIT();
    ISSUEB(2, 2); CP_COMMIT();
    ISSUEB(3, 3); CP_COMMIT();
    ISSUEB(4, 4); CP_COMMIT();

    float acc[4][4][4];
#pragma unroll
    for (int i = 0; i < 4; i++)
#pragma unroll
        for (int j = 0; j < 4; j++)
#pragma unroll
            for (int p = 0; p < 4; p++) acc[i][j][p] = 0.f;

    // ldsm.trans A addressing (proven, 528B k-row stride within a buffer).
    const uint32_t aOff = (uint32_t)(((lane & 7) + ((lane >> 4) & 1) * 8) * 528
                                     + (warp_m * 64 + ((lane >> 3) & 1) * 8) * 2);
    // ldsm B addressing (proven, 48B rows within a stage).
    const uint32_t bOff = (uint32_t)((warp_n * 32 + (lane & 7) + ((lane >> 4) << 3)) * 48
                                     + ((lane >> 3) & 1) * 16);

    uint32_t bF[2][2][4];

    CP_WAIT(4);
    __syncthreads();                   // buf0 A STS + B stage0 visible
    ldsm4(bF[0][0], sb + B_OFF + bOff);
    ldsm4(bF[0][1], sb + B_OFF + bOff + 16 * 48);

#define STEP(c, n, kc)                                                     \
    do {                                                                   \
        if ((kc) + 1 < 48) {                                               \
            CP_WAIT(3);                                                    \
            __syncthreads();                                               \
            const uint32_t stn = sb + B_OFF + (((kc) + 1) & 7) * B_STG;    \
            ldsm4(bF[n][0], stn + bOff);                                   \
            ldsm4(bF[n][1], stn + bOff + 16 * 48);                         \
            if ((kc) + 5 < 48) ISSUEB((kc) + 5, ((kc) + 5) & 7);           \
            CP_COMMIT();                                                   \
            __half* ab = (((kc) + 1) & 1) ? asm1 : asm0;                   \
            _Pragma("unroll")                                              \
            for (int r = 0; r < 16; r++)                                   \
                ab[r * 264 + tid] = __float2half(areg[r]);                 \
            if ((kc) + 2 < 48) {                                           \
                _Pragma("unroll")                                          \
                for (int r = 0; r < 16; r++)                               \
                    areg[r] = __ldg(fb + (size_t)(((kc) + 2) * 16 + r) * N_); \
            }                                                              \
        }                                                                  \
        const uint32_t stA = sb + ((kc) & 1) * A_BUF;                      \
        _Pragma("unroll")                                                  \
        for (int mt = 0; mt < 4; mt++) {                                   \
            uint32_t ah[4];                                                \
            ldsm4t(ah, stA + aOff + mt * 32);                              \
            _Pragma("unroll")                                              \
            for (int nt = 0; nt < 4; nt++)                                 \
                mma_f16(acc[mt][nt], ah,                                   \
                        &bF[c][nt >> 1][(nt & 1) * 2]);                    \
        }                                                                  \
    } while (0)

#pragma unroll 1
    for (int kc = 0; kc < 48; kc += 2) {
        STEP(0, 1, kc);
        STEP(1, 0, kc + 1);
    }

    // Epilogue (unchanged)
    const int g  = lane >> 2;
    const int t4 = lane & 3;
#pragma unroll
    for (int mt = 0; mt < 4; mt++) {
        const int m = m0 + warp_m * 64 + mt * 16 + g;
        const int slo = m & 1023;
#pragma unroll
        for (int nt = 0; nt < 4; nt++) {
            const int n = n0 + warp_n * 32 + nt * 8 + t4 * 2;
            const float b0v = __ldg(bias + n);
            const float b1v = __ldg(bias + n + 1);
            float* o0 = out + ((size_t)(b * O_ + n)) * S_ + slo;
            float* o1 = out + ((size_t)(b * O_ + n + 1)) * S_ + slo;
            o0[0] = acc[mt][nt][0] + b0v;
            o1[0] = acc[mt][nt][1] + b1v;
            o0[8] = acc[mt][nt][2] + b0v;
            o1[8] = acc[mt][nt][3] + b1v;
        }
    }
}

// ---------------------------------------------------------------------------
extern "C" void kernel_launch(void* const* d_in, const int* in_sizes, int n_in,
                              void* d_out, int out_size) {
    const float* seed = (const float*)d_in[0];   // [16,1024,3]
    const float* pl   = (const float*)d_in[1];   // [16,4096,3]
    const float* fl   = (const float*)d_in[2];   // [16,768,4096]
    const float* Wt   = (const float*)d_in[3];   // [256,768]
    const float* bias = (const float*)d_in[4];   // [256]
    float* out = (float*)d_out;                  // [16,256,1024]

    cudaFuncSetAttribute(argmin_kernel, cudaFuncAttributeMaxDynamicSharedMemorySize, 65536);
    cudaFuncSetAttribute(gemm_kernel, cudaFuncAttributeMaxDynamicSharedMemorySize, GEMM_SMEM);

    argmin_kernel<<<256, 256, 65536>>>(seed, pl);
    wconv_kernel<<<(O_ * C_ + 255) / 256, 256>>>(Wt);
    gemm_kernel<<<dim3(O_ / 64, M_ / 256), 256, GEMM_SMEM>>>(fl, bias, out);
}

// round 17
// speedup vs baseline: 2.5300x; 2.5300x over previous
#include <cuda_runtime.h>
#include <cuda_bf16.h>
#include <cuda_fp16.h>
#include <cstdint>

#define B_ 16
#define S_ 1024
#define N_ 4096
#define C_ 768
#define O_ 256
#define M_ (B_ * S_)   // 16384

// ---------------------------------------------------------------------------
// Scratch (__device__ globals; allocation-free rule). A is K-MAJOR, fp16.
// ---------------------------------------------------------------------------
typedef unsigned long long ull;
__device__ ull      g_key[M_];
__device__ int      g_idx[M_];
__device__ __half   g_Af[(size_t)C_ * M_];
__device__ __half   g_Bf[O_ * C_];

// ---------------------------------------------------------------------------
// Base-ISA (compute_103-safe) PTX helpers
// ---------------------------------------------------------------------------
__device__ __forceinline__ uint32_t smem_u32(const void* p) {
    uint32_t a;
    asm("{ .reg .u64 t; cvta.to.shared.u64 t, %1; cvt.u32.u64 %0, t; }" : "=r"(a) : "l"(p));
    return a;
}
__device__ __forceinline__ void cp16(uint32_t dst, const void* src) {
    asm volatile("cp.async.cg.shared.global [%0], [%1], 16;"
                 :: "r"(dst), "l"(src) : "memory");
}
#define CP_COMMIT() asm volatile("cp.async.commit_group;" ::: "memory")
#define CP_WAIT(n)  asm volatile("cp.async.wait_group %0;" :: "n"(n) : "memory")

__device__ __forceinline__ void ldsm4(uint32_t* r, uint32_t addr) {
    asm volatile("ldmatrix.sync.aligned.m8n8.x4.shared.b16 {%0,%1,%2,%3}, [%4];"
                 : "=r"(r[0]), "=r"(r[1]), "=r"(r[2]), "=r"(r[3]) : "r"(addr));
}
__device__ __forceinline__ void ldsm4t(uint32_t* r, uint32_t addr) {
    asm volatile("ldmatrix.sync.aligned.m8n8.x4.trans.shared.b16 {%0,%1,%2,%3}, [%4];"
                 : "=r"(r[0]), "=r"(r[1]), "=r"(r[2]), "=r"(r[3]) : "r"(addr));
}
__device__ __forceinline__ void mma_f16(float* c, const uint32_t* a, const uint32_t* b) {
    asm volatile("mma.sync.aligned.m16n8k16.row.col.f32.f16.f16.f32 "
                 "{%0,%1,%2,%3}, {%4,%5,%6,%7}, {%8,%9}, {%0,%1,%2,%3};"
                 : "+f"(c[0]), "+f"(c[1]), "+f"(c[2]), "+f"(c[3])
                 : "r"(a[0]), "r"(a[1]), "r"(a[2]), "r"(a[3]), "r"(b[0]), "r"(b[1]));
}

// ---- packed fp32x2 (per-lane IEEE rn, identical to __fmul_rn/__fadd_rn) ----
__device__ __forceinline__ ull pk2(float a, float b) {
    ull r;
    asm("mov.b64 %0, {%1, %2};" : "=l"(r) : "r"(__float_as_uint(a)), "r"(__float_as_uint(b)));
    return r;
}
__device__ __forceinline__ ull bc2(float v) {
    ull r;
    asm("mov.b64 %0, {%1, %1};" : "=l"(r) : "r"(__float_as_uint(v)));
    return r;
}
__device__ __forceinline__ ull mul2(ull a, ull b) {
    ull d; asm("mul.rn.f32x2 %0, %1, %2;" : "=l"(d) : "l"(a), "l"(b)); return d;
}
__device__ __forceinline__ ull add2(ull a, ull b) {
    ull d; asm("add.rn.f32x2 %0, %1, %2;" : "=l"(d) : "l"(a), "l"(b)); return d;
}
__device__ __forceinline__ ull sub2(ull a, ull b) {
    return add2(a, b ^ 0x8000000080000000ull);
}
__device__ __forceinline__ void unpk2(float& lo, float& hi, ull v) {
    unsigned a, b;
    asm("mov.b64 {%0, %1}, %2;" : "=r"(a), "=r"(b) : "l"(v));
    lo = __uint_as_float(a); hi = __uint_as_float(b);
}
__device__ __forceinline__ ull mkkey(float d2, int n) {
    const unsigned u = __float_as_uint(d2);
    const unsigned ord = u ^ (((unsigned)((int)u >> 31)) | 0x80000000u);
    return ((ull)ord << 32) | (unsigned)n;
}

// ---------------------------------------------------------------------------
// Kernel 1: argmin, 4x point-split + atomicMin(u64) merge.
// Grid 1024: bx -> b = bx>>6, g = bx&63; sbase = (g&15)*64 seeds,
// point slice = (g>>4)*1024. Per-point arithmetic identical (f32x2, exact
// unfused mul/add). Keys (ord(d2)<<32 | n) are unique in n; min is
// commutative -> result bit-identical to the sequential argmin.
// smem: 1024 float4 (16KB) + merge 4KB -> ~8 blocks/SM, one wave.
// ---------------------------------------------------------------------------
__global__ __launch_bounds__(256) void argmin_kernel(const float* __restrict__ seed,
                                                     const float* __restrict__ pl) {
    __shared__ float4 p4[1024];
    __shared__ ull mg[8][64];
    const int bx   = blockIdx.x;
    const int b    = bx >> 6;
    const int g    = bx & 63;
    const int tid  = threadIdx.x;
    const int w    = tid >> 5;
    const int lane = tid & 31;
    const int sbase = (g & 15) << 6;
    const int np0   = (g >> 4) << 10;              // point slice base

    for (int i = tid; i < 1024; i += 256) {
        const int n = np0 + i;
        const float* pp = pl + ((size_t)b * N_ + n) * 3;
        const float p0 = pp[0], p1 = pp[1], p2 = pp[2];
        const float spp = __fadd_rn(__fadd_rn(__fmul_rn(p0, p0), __fmul_rn(p1, p1)),
                                    __fmul_rn(p2, p2));
        p4[i] = make_float4(p0, p1, p2, spp);
    }

    const float* sa = seed + ((size_t)b * S_ + sbase + lane) * 3;
    const float* sc = seed + ((size_t)b * S_ + sbase + 32 + lane) * 3;
    const float xa0 = sa[0], xa1 = sa[1], xa2 = sa[2];
    const float xb0 = sc[0], xb1 = sc[1], xb2 = sc[2];
    const float sxa = __fadd_rn(__fadd_rn(__fmul_rn(xa0, xa0), __fmul_rn(xa1, xa1)),
                                __fmul_rn(xa2, xa2));
    const float sxb = __fadd_rn(__fadd_rn(__fmul_rn(xb0, xb0), __fmul_rn(xb1, xb1)),
                                __fmul_rn(xb2, xb2));
    const ull X0 = pk2(xa0, xb0), X1 = pk2(xa1, xb1), X2 = pk2(xa2, xb2);
    const ull SX = pk2(sxa, sxb);
    __syncthreads();

    float bestA[2] = {3.402823466e38f, 3.402823466e38f};
    float bestB[2] = {3.402823466e38f, 3.402823466e38f};
    int   iA[2] = {0, 0}, iB[2] = {0, 0};

    const int nb = w * 128;                        // local slice for this warp
#pragma unroll 2
    for (int n0 = 0; n0 < 128; n0 += 2) {
#pragma unroll
        for (int j = 0; j < 2; j++) {
            const int i = nb + n0 + j;
            const float4 q = p4[i];
            const ull QX = bc2(q.x), QY = bc2(q.y), QZ = bc2(q.z), QW = bc2(q.w);
            const ull DOT = add2(add2(mul2(X0, QX), mul2(X1, QY)), mul2(X2, QZ));
            const ull D2  = add2(sub2(SX, add2(DOT, DOT)), QW);
            float d2a, d2b;
            unpk2(d2a, d2b, D2);
            if (d2a < bestA[j]) { bestA[j] = d2a; iA[j] = np0 + i; }
            if (d2b < bestB[j]) { bestB[j] = d2b; iB[j] = np0 + i; }
        }
    }

    ull ka = mkkey(bestA[0], iA[0]);
    { const ull k1 = mkkey(bestA[1], iA[1]); if (k1 < ka) ka = k1; }
    ull kb = mkkey(bestB[0], iB[0]);
    { const ull k1 = mkkey(bestB[1], iB[1]); if (k1 < kb) kb = k1; }
    mg[w][lane]      = ka;
    mg[w][lane + 32] = kb;
    __syncthreads();

    if (tid < 64) {
        ull k = mg[0][tid];
#pragma unroll
        for (int r = 1; r < 8; r++) { const ull k2 = mg[r][tid]; if (k2 < k) k = k2; }
        atomicMin(&g_key[b * S_ + sbase + tid], k);
    }
}

// ---------------------------------------------------------------------------
// Kernel 1b: extract idx from keys.
// ---------------------------------------------------------------------------
__global__ __launch_bounds__(256) void extract_kernel() {
    const int i = blockIdx.x * 256 + threadIdx.x;
    g_idx[i] = (int)(g_key[i] & 0xFFFFFFFFu);
}

// ---------------------------------------------------------------------------
// Kernel 2: gather, 1 channel/block (proven round-15 version).
// ---------------------------------------------------------------------------
__global__ __launch_bounds__(128) void gather_kernel(const float* __restrict__ f) {
    extern __shared__ char gs[];
    float* row  = reinterpret_cast<float*>(gs);            // 4096 floats
    int*   sidx = reinterpret_cast<int*>(gs + 16384);      // 1024 ints
    const uint32_t sb = smem_u32(gs);
    const int bx  = blockIdx.x;
    const int b   = bx / 768;
    const int c   = bx - b * 768;
    const int tid = threadIdx.x;

    const char* src = reinterpret_cast<const char*>(f) + (size_t)bx * 16384;

#pragma unroll
    for (int i = 0; i < 8; i++)
        cp16(sb + (tid + i * 128) * 16, src + (size_t)(tid + i * 128) * 16);
#pragma unroll
    for (int i = 0; i < 2; i++)
        cp16(sb + 16384 + (tid + i * 128) * 16, &g_idx[b * S_ + (tid + i * 128) * 4]);
    CP_COMMIT();
    CP_WAIT(0);
    __syncthreads();

    const int4 ia = reinterpret_cast<const int4*>(sidx)[tid * 2];
    const int4 ib = reinterpret_cast<const int4*>(sidx)[tid * 2 + 1];

    const __half h0 = __float2half(row[ia.x]);
    const __half h1 = __float2half(row[ia.y]);
    const __half h2 = __float2half(row[ia.z]);
    const __half h3 = __float2half(row[ia.w]);
    const __half h4 = __float2half(row[ib.x]);
    const __half h5 = __float2half(row[ib.y]);
    const __half h6 = __float2half(row[ib.z]);
    const __half h7 = __float2half(row[ib.w]);

    uint4 pk;
    pk.x = (uint32_t)__half_as_ushort(h0) | ((uint32_t)__half_as_ushort(h1) << 16);
    pk.y = (uint32_t)__half_as_ushort(h2) | ((uint32_t)__half_as_ushort(h3) << 16);
    pk.z = (uint32_t)__half_as_ushort(h4) | ((uint32_t)__half_as_ushort(h5) << 16);
    pk.w = (uint32_t)__half_as_ushort(h6) | ((uint32_t)__half_as_ushort(h7) << 16);
    *reinterpret_cast<uint4*>(&g_Af[(size_t)c * M_ + b * S_ + tid * 8]) = pk;
}

// ---------------------------------------------------------------------------
// Kernel 2b: round W to fp16 + init g_key sentinels (runs BEFORE argmin).
// ---------------------------------------------------------------------------
__global__ __launch_bounds__(256) void wconv_kernel(const float* __restrict__ W) {
    const int i = blockIdx.x * 256 + threadIdx.x;
    if (i < O_ * C_) g_Bf[i] = __float2half(W[i]);
    if (i < M_) g_key[i] = ~0ull;
}

// ---------------------------------------------------------------------------
// Kernel 3: mma.sync fp16 GEMM (proven round-14 version).
// CTA 256m x 64n, warp tile m64 x n32, k16 chunks, 8-stage ring, 2 CTAs/SM.
// ---------------------------------------------------------------------------
#define ARR_AF 0
#define ARR_BF 8448
#define STAGE  11520
#define NSTG   8
#define GEMM_SMEM (NSTG * STAGE)

__global__ __launch_bounds__(256, 2) void gemm_kernel(const float* __restrict__ bias,
                                                      float* __restrict__ out) {
    extern __shared__ char smem[];
    const uint32_t sb = smem_u32(smem);
    const int tid  = threadIdx.x;
    const int lane = tid & 31;
    const int wid  = tid >> 5;
    const int warp_m = wid & 3;
    const int warp_n = wid >> 2;
    const int m0 = blockIdx.x * 256;
    const int n0 = blockIdx.y * 64;

    const int akrow = tid >> 4;
    const int aseg  = tid & 15;
    const __half* gA = g_Af + (size_t)akrow * M_ + m0 + aseg * 8;
    const uint32_t dA = (uint32_t)(akrow * 528 + aseg * 16);
    const int brow = (tid >> 1) & 63;
    const int bseg = tid & 1;
    const bool bact = tid < 128;
    const __half* gB = g_Bf + (size_t)(n0 + brow) * C_ + bseg * 8;
    const uint32_t dB = (uint32_t)(brow * 48 + bseg * 16);

#define ISSUE(kc, stg)                                                    \
    do {                                                                  \
        const uint32_t s0 = sb + (stg) * STAGE;                           \
        const size_t ga = (size_t)(kc) * (16 * M_);                       \
        cp16(s0 + ARR_AF + dA,       gA + ga);                            \
        cp16(s0 + ARR_AF + dA + 256, gA + ga + 128);                      \
        if (bact) cp16(s0 + ARR_BF + dB, gB + (kc) * 16);                 \
    } while (0)

    ISSUE(0, 0); CP_COMMIT();
    ISSUE(1, 1); CP_COMMIT();
    ISSUE(2, 2); CP_COMMIT();
    ISSUE(3, 3); CP_COMMIT();
    ISSUE(4, 4); CP_COMMIT();

    float acc[4][4][4];
#pragma unroll
    for (int i = 0; i < 4; i++)
#pragma unroll
        for (int j = 0; j < 4; j++)
#pragma unroll
            for (int p = 0; p < 4; p++) acc[i][j][p] = 0.f;

    const uint32_t aOff = (uint32_t)(((lane & 7) + ((lane >> 4) & 1) * 8) * 528
                                     + (warp_m * 64 + ((lane >> 3) & 1) * 8) * 2);
    const uint32_t bOff = (uint32_t)((warp_n * 32 + (lane & 7) + ((lane >> 4) << 3)) * 48
                                     + ((lane >> 3) & 1) * 16);

    uint32_t bF[2][2][4];

    CP_WAIT(4);
    __syncthreads();
    ldsm4(bF[0][0], sb + ARR_BF + bOff);
    ldsm4(bF[0][1], sb + ARR_BF + bOff + 16 * 48);

#define STEP(c, n, kc)                                                     \
    do {                                                                   \
        if ((kc) + 1 < 48) {                                               \
            CP_WAIT(3);                                                    \
            __syncthreads();                                               \
            const uint32_t stn = sb + (((kc) + 1) & 7) * STAGE;            \
            ldsm4(bF[n][0], stn + ARR_BF + bOff);                          \
            ldsm4(bF[n][1], stn + ARR_BF + bOff + 16 * 48);                \
            if ((kc) + 5 < 48) ISSUE((kc) + 5, ((kc) + 5) & 7);            \
            CP_COMMIT();                                                   \
        }                                                                  \
        const uint32_t stc = sb + ((kc) & 7) * STAGE;                      \
        _Pragma("unroll")                                                  \
        for (int mt = 0; mt < 4; mt++) {                                   \
            uint32_t ah[4];                                                \
            ldsm4t(ah, stc + ARR_AF + aOff + mt * 32);                     \
            _Pragma("unroll")                                              \
            for (int nt = 0; nt < 4; nt++)                                 \
                mma_f16(acc[mt][nt], ah,                                   \
                        &bF[c][nt >> 1][(nt & 1) * 2]);                    \
        }                                                                  \
    } while (0)

#pragma unroll 1
    for (int kc = 0; kc < 48; kc += 2) {
        STEP(0, 1, kc);
        STEP(1, 0, kc + 1);
    }

    const int g  = lane >> 2;
    const int t4 = lane & 3;
    const int bbatch = m0 >> 10;
#pragma unroll
    for (int mt = 0; mt < 4; mt++) {
        const int m = m0 + warp_m * 64 + mt * 16 + g;
        const int slo = m & 1023;
#pragma unroll
        for (int nt = 0; nt < 4; nt++) {
            const int n = n0 + warp_n * 32 + nt * 8 + t4 * 2;
            const float b0v = __ldg(bias + n);
            const float b1v = __ldg(bias + n + 1);
            float* o0 = out + ((size_t)(bbatch * O_ + n)) * S_ + slo;
            float* o1 = out + ((size_t)(bbatch * O_ + n + 1)) * S_ + slo;
            o0[0] = acc[mt][nt][0] + b0v;
            o1[0] = acc[mt][nt][1] + b1v;
            o0[8] = acc[mt][nt][2] + b0v;
            o1[8] = acc[mt][nt][3] + b1v;
        }
    }
}

// ---------------------------------------------------------------------------
extern "C" void kernel_launch(void* const* d_in, const int* in_sizes, int n_in,
                              void* d_out, int out_size) {
    const float* seed = (const float*)d_in[0];   // [16,1024,3]
    const float* pl   = (const float*)d_in[1];   // [16,4096,3]
    const float* fl   = (const float*)d_in[2];   // [16,768,4096]
    const float* Wt   = (const float*)d_in[3];   // [256,768]
    const float* bias = (const float*)d_in[4];   // [256]
    float* out = (float*)d_out;                  // [16,256,1024]

    cudaFuncSetAttribute(gather_kernel, cudaFuncAttributeMaxDynamicSharedMemorySize, 20480);
    cudaFuncSetAttribute(gemm_kernel, cudaFuncAttributeMaxDynamicSharedMemorySize, GEMM_SMEM);

    wconv_kernel<<<(O_ * C_ + 255) / 256, 256>>>(Wt);   // also inits g_key
    argmin_kernel<<<1024, 256>>>(seed, pl);
    extract_kernel<<<M_ / 256, 256>>>();
    gather_kernel<<<B_ * C_, 128, 20480>>>(fl);
    gemm_kernel<<<dim3(M_ / 256, O_ / 64), 256, GEMM_SMEM>>>(bias, out);
}